// round 8
// baseline (speedup 1.0000x reference)
#include <cuda_runtime.h>
#include <math.h>

typedef unsigned long long ull;

namespace {
constexpr int NT   = 1024;
constexpr int XSTR = 68;     // padded row stride (floats) for X/G buffer
constexpr int VSTR = 520;    // padded vT stride
constexpr int LRES = 1024;
constexpr float LN_EPS = 1e-5f;

struct __align__(16) Smem {
    float xg[512 * XSTR];      // 139264 B: X row-major padded, then G in place
    float wc[64][80];          // 20480 B: cols 0-63 Wg, 64-71 Wk, 72-79 Wv
    float wo[64 * 64];         // 16384 B (ovec-folded before pass B)
    float kbuf[512 * 8];       // 16384 B: k; later scores[8][512]
    float vT[8 * VSTR];        // 16640 B
    float lnw[64], lnb[64], bgv[64], bov[64], xsum[64], qvec[64];
    float xpart[16 * 64];      // 4096 B
    float mpart[16], spart[16], opart[16][8], ovec[64];
};  // ~215.7 KB

__device__ __forceinline__ void ffma2(ull& d_, ull a, ull b) {
    asm("fma.rn.f32x2 %0, %1, %2, %0;" : "+l"(d_) : "l"(a), "l"(b));
}
__device__ __forceinline__ ull splat2(float x) {
    ull r; asm("mov.b64 %0, {%1, %1};" : "=l"(r) : "f"(x)); return r;
}
__device__ __forceinline__ ull add2(ull a, ull b) {
    ull r; asm("add.rn.f32x2 %0, %1, %2;" : "=l"(r) : "l"(a), "l"(b)); return r;
}
__device__ __forceinline__ void unpack2(ull u, float& lo, float& hi) {
    asm("mov.b64 {%0, %1}, %2;" : "=f"(lo), "=f"(hi) : "l"(u));
}
__device__ __forceinline__ float sigmoid_fast(float v) {
    return __fdividef(1.f, 1.f + __expf(-v));
}
} // namespace

__global__ void __launch_bounds__(NT, 1)
msa_col_attn_v8(const float* __restrict__ msa,
                const float* __restrict__ g_lnw, const float* __restrict__ g_lnb,
                const float* __restrict__ g_wq,  const float* __restrict__ g_wk,
                const float* __restrict__ g_wv,  const float* __restrict__ g_wg,
                const float* __restrict__ g_bg,  const float* __restrict__ g_wo,
                const float* __restrict__ g_bo,  float* __restrict__ out)
{
    extern __shared__ float smf[];
    Smem* s = reinterpret_cast<Smem*>(smf);
    const int tid  = threadIdx.x;
    const int l    = blockIdx.x;
    const int lane = tid & 31;
    const int wid  = tid >> 5;

    // ---------------- preamble ----------------
    {
        int d = tid >> 4, c4 = (tid & 15) * 4;   // Wg: 4 per thread
        float4 wg4 = *reinterpret_cast<const float4*>(g_wg + d * 64 + c4);
        *reinterpret_cast<float4*>(&s->wc[d][c4]) = wg4;
        if (tid < 512) {
            int dd = tid >> 3, j = tid & 7;
            s->wc[dd][64 + j] = g_wk[tid];
            s->wc[dd][72 + j] = g_wv[tid];
        }
        ((float4*)s->wo)[tid] = ((const float4*)g_wo)[tid];
        if (tid < 64) {
            s->lnw[tid] = g_lnw[tid];
            s->lnb[tid] = g_lnb[tid];
            s->bgv[tid] = g_bg[tid];
            s->bov[tid] = g_bo[tid];
        }
    }
    __syncthreads();

    // ---------------- LayerNorm: 512x64 -> xg row-major (stride 68) ----------------
    {
        const int lrow = tid >> 2;      // 0..255 (and +256)
        const int lq   = tid & 3;       // 16 cols each
        const float* b0 = msa + ((size_t)lrow * LRES + l) * 64 + lq * 16;
        const float* b1 = b0 + (size_t)256 * LRES * 64;
        float4 r0[4], r1[4];
        #pragma unroll
        for (int j = 0; j < 4; ++j) r0[j] = ((const float4*)b0)[j];
        #pragma unroll
        for (int j = 0; j < 4; ++j) r1[j] = ((const float4*)b1)[j];

        #pragma unroll
        for (int half = 0; half < 2; ++half) {
            float4* rr = half ? r1 : r0;
            int row = lrow + half * 256;
            float sm = 0.f, sq = 0.f;
            #pragma unroll
            for (int j = 0; j < 4; ++j) {
                float4 t = rr[j];
                sm += (t.x + t.y) + (t.z + t.w);
                sq  = fmaf(t.x, t.x, fmaf(t.y, t.y, fmaf(t.z, t.z, fmaf(t.w, t.w, sq))));
            }
            sm += __shfl_xor_sync(0xffffffffu, sm, 1);
            sq += __shfl_xor_sync(0xffffffffu, sq, 1);
            sm += __shfl_xor_sync(0xffffffffu, sm, 2);
            sq += __shfl_xor_sync(0xffffffffu, sq, 2);
            float mu   = sm * (1.f / 64.f);
            float var  = sq * (1.f / 64.f) - mu * mu;
            float rstd = rsqrtf(var + LN_EPS);
            float mrs  = -mu * rstd;
            float* dst = s->xg + row * XSTR + lq * 16;
            #pragma unroll
            for (int j = 0; j < 4; ++j) {
                int c0 = lq * 16 + 4 * j;
                float4 t = rr[j], v;
                v.x = fmaf(fmaf(t.x, rstd, mrs), s->lnw[c0 + 0], s->lnb[c0 + 0]);
                v.y = fmaf(fmaf(t.y, rstd, mrs), s->lnw[c0 + 1], s->lnb[c0 + 1]);
                v.z = fmaf(fmaf(t.z, rstd, mrs), s->lnw[c0 + 2], s->lnb[c0 + 2]);
                v.w = fmaf(fmaf(t.w, rstd, mrs), s->lnw[c0 + 3], s->lnb[c0 + 3]);
                *reinterpret_cast<float4*>(dst + 4 * j) = v;
            }
        }
    }
    __syncthreads();

    // ---------------- xsum partials (reads xg) ----------------
    {
        const int c = tid & 63, seg = tid >> 6;
        const float* xp = s->xg + (seg * 32) * XSTR + c;
        float t = 0.f;
        #pragma unroll 8
        for (int i = 0; i < 32; ++i) t += xp[i * XSTR];
        s->xpart[seg * 64 + c] = t;
    }

    const int rg = tid >> 3;    // rows 4rg..4rg+3
    const int cg = tid & 7;

    // ---------------- kv GEMM (4 rows x 1 col-pair), store immediately ----------------
    {
        ull ka[4] = {0, 0, 0, 0};
        const float* xb = s->xg + 4 * rg * XSTR;
        const float* wb = &s->wc[0][64 + 2 * cg];
        #pragma unroll 8
        for (int d = 0; d < 64; ++d) {
            ull w2 = *reinterpret_cast<const ull*>(wb + 80 * d);
            float x0 = xb[d], x1 = xb[XSTR + d], x2 = xb[2 * XSTR + d], x3 = xb[3 * XSTR + d];
            ffma2(ka[0], splat2(x0), w2);
            ffma2(ka[1], splat2(x1), w2);
            ffma2(ka[2], splat2(x2), w2);
            ffma2(ka[3], splat2(x3), w2);
        }
        if (cg < 4) {
            #pragma unroll
            for (int i = 0; i < 4; ++i)
                *reinterpret_cast<ull*>(&s->kbuf[(4 * rg + i) * 8 + 2 * cg]) = ka[i];
        } else {
            int c0 = 2 * (cg - 4);
            float a[4], b[4];
            #pragma unroll
            for (int i = 0; i < 4; ++i) unpack2(ka[i], a[i], b[i]);
            *reinterpret_cast<float4*>(&s->vT[c0 * VSTR + 4 * rg])       = make_float4(a[0], a[1], a[2], a[3]);
            *reinterpret_cast<float4*>(&s->vT[(c0 + 1) * VSTR + 4 * rg]) = make_float4(b[0], b[1], b[2], b[3]);
        }
    }
    __syncthreads();

    // xsum reduce (xpart complete)
    if (tid < 64) {
        float t = 0.f;
        #pragma unroll
        for (int w = 0; w < 16; ++w) t += s->xpart[w * 64 + tid];
        s->xsum[tid] = t;
    }

    // ---------------- gate GEMM: 4 rows x 8 cols ----------------
    ull ga[4][4];
    #pragma unroll
    for (int i = 0; i < 4; ++i)
        #pragma unroll
        for (int p = 0; p < 4; ++p) ga[i][p] = 0;
    {
        const float* xb = s->xg + 4 * rg * XSTR;
        const float* wb = &s->wc[0][8 * cg];
        #pragma unroll 4
        for (int d = 0; d < 64; ++d) {
            ulonglong2 w0 = *reinterpret_cast<const ulonglong2*>(wb + 80 * d);
            ulonglong2 w1 = *reinterpret_cast<const ulonglong2*>(wb + 80 * d + 4);
            float x0 = xb[d], x1 = xb[XSTR + d], x2 = xb[2 * XSTR + d], x3 = xb[3 * XSTR + d];
            ull t;
            t = splat2(x0); ffma2(ga[0][0],t,w0.x); ffma2(ga[0][1],t,w0.y); ffma2(ga[0][2],t,w1.x); ffma2(ga[0][3],t,w1.y);
            t = splat2(x1); ffma2(ga[1][0],t,w0.x); ffma2(ga[1][1],t,w0.y); ffma2(ga[1][2],t,w1.x); ffma2(ga[1][3],t,w1.y);
            t = splat2(x2); ffma2(ga[2][0],t,w0.x); ffma2(ga[2][1],t,w0.y); ffma2(ga[2][2],t,w1.x); ffma2(ga[2][3],t,w1.y);
            t = splat2(x3); ffma2(ga[3][0],t,w0.x); ffma2(ga[3][1],t,w0.y); ffma2(ga[3][2],t,w1.x); ffma2(ga[3][3],t,w1.y);
        }
    }
    __syncthreads();   // all xg reads done; xsum visible

    // ---------------- gate epilogue: G = sigmoid(P + bg) -> xg in place ----------------
    {
        float bb[8];
        #pragma unroll
        for (int k = 0; k < 8; ++k) bb[k] = s->bgv[8 * cg + k];
        #pragma unroll
        for (int i = 0; i < 4; ++i) {
            float g[8];
            #pragma unroll
            for (int p = 0; p < 4; ++p) {
                float lo, hi;
                unpack2(ga[i][p], lo, hi);
                g[2 * p]     = sigmoid_fast(lo + bb[2 * p]);
                g[2 * p + 1] = sigmoid_fast(hi + bb[2 * p + 1]);
            }
            float* dst = s->xg + (4 * rg + i) * XSTR + 8 * cg;
            *reinterpret_cast<float4*>(dst)     = make_float4(g[0], g[1], g[2], g[3]);
            *reinterpret_cast<float4*>(dst + 4) = make_float4(g[4], g[5], g[6], g[7]);
        }
    }
    // qvec partials (xsum ready since last barrier)
    {
        int dg = tid >> 6, c = tid & 63;
        float p = 0.f;
        #pragma unroll
        for (int i = 0; i < 4; ++i)
            p = fmaf(s->xsum[4 * dg + i], g_wq[(4 * dg + i) * 64 + c], p);
        s->xpart[dg * 64 + c] = p;
    }
    __syncthreads();

    // qvec reduce + k into regs (kbuf dies after next barrier)
    if (tid < 64) {
        float q = 0.f;
        #pragma unroll
        for (int dg = 0; dg < 16; ++dg) q += s->xpart[dg * 64 + tid];
        s->qvec[tid] = q * (float)(0.35355339059327373 / 512.0); // (1/sqrt(8))/N
    }
    const int sn = tid & 511, hh = tid >> 9;
    float4 k0 = *reinterpret_cast<const float4*>(&s->kbuf[sn * 8]);
    float4 k1 = *reinterpret_cast<const float4*>(&s->kbuf[sn * 8 + 4]);
    __syncthreads();

    // ---------------- scores (overlay kbuf) ----------------
    {
        float* sc = s->kbuf;
        #pragma unroll
        for (int j = 0; j < 4; ++j) {
            int h = 4 * hh + j;
            const float* qf = &s->qvec[8 * h];
            float v = qf[0]*k0.x + qf[1]*k0.y + qf[2]*k0.z + qf[3]*k0.w
                    + qf[4]*k1.x + qf[5]*k1.y + qf[6]*k1.z + qf[7]*k1.w;
            sc[h * 512 + sn] = v;
        }
    }
    __syncthreads();

    // ---------------- softmax partials: 2 warps per head ----------------
    if (wid < 16) {
        int h = wid >> 1, half = wid & 1;
        const float* sc = s->kbuf + h * 512 + half * 256;
        const float* vT = s->vT;
        float sv[8], m = -1e30f;
        #pragma unroll
        for (int k = 0; k < 8; ++k) { sv[k] = sc[lane + 32 * k]; m = fmaxf(m, sv[k]); }
        #pragma unroll
        for (int off = 16; off > 0; off >>= 1)
            m = fmaxf(m, __shfl_xor_sync(0xffffffffu, m, off));
        float ssum = 0.f, acc[8];
        #pragma unroll
        for (int d = 0; d < 8; ++d) acc[d] = 0.f;
        #pragma unroll
        for (int k = 0; k < 8; ++k) {
            float e = __expf(sv[k] - m);
            ssum += e;
            int n = half * 256 + lane + 32 * k;
            #pragma unroll
            for (int d = 0; d < 8; ++d) acc[d] = fmaf(e, vT[d * VSTR + n], acc[d]);
        }
        #pragma unroll
        for (int off = 16; off > 0; off >>= 1) {
            ssum += __shfl_xor_sync(0xffffffffu, ssum, off);
            #pragma unroll
            for (int d = 0; d < 8; ++d) acc[d] += __shfl_xor_sync(0xffffffffu, acc[d], off);
        }
        if (lane == 0) {
            s->mpart[wid] = m;
            s->spart[wid] = ssum;
            #pragma unroll
            for (int d = 0; d < 8; ++d) s->opart[wid][d] = acc[d];
        }
    }
    __syncthreads();

    // ovec combine (exact two-way softmax merge)
    if (tid < 64) {
        int h = tid >> 3, d = tid & 7;
        float m0 = s->mpart[2 * h], m1 = s->mpart[2 * h + 1];
        float m = fmaxf(m0, m1);
        float e0 = __expf(m0 - m), e1 = __expf(m1 - m);
        float ss = s->spart[2 * h] * e0 + s->spart[2 * h + 1] * e1;
        float ov = s->opart[2 * h][d] * e0 + s->opart[2 * h + 1][d] * e1;
        s->ovec[8 * h + d] = ov / ss;
    }
    __syncthreads();

    // fold ovec into Wo rows (1 float4 per thread)
    {
        float4 w4 = ((float4*)s->wo)[tid];
        float ov = s->ovec[tid >> 4];
        w4.x *= ov; w4.y *= ov; w4.z *= ov; w4.w *= ov;
        ((float4*)s->wo)[tid] = w4;
    }
    __syncthreads();

    // ---------------- pass B: out = G @ Wo' + bo ----------------
    {
        ull acc[4][4];
        #pragma unroll
        for (int i = 0; i < 4; ++i)
            #pragma unroll
            for (int p = 0; p < 4; ++p) acc[i][p] = 0;
        const float* gb = s->xg + 4 * rg * XSTR;
        const float* wb = s->wo + 8 * cg;
        #pragma unroll 4
        for (int d = 0; d < 64; ++d) {
            ulonglong2 w0 = *reinterpret_cast<const ulonglong2*>(wb + 64 * d);
            ulonglong2 w1 = *reinterpret_cast<const ulonglong2*>(wb + 64 * d + 4);
            float x0 = gb[d], x1 = gb[XSTR + d], x2 = gb[2 * XSTR + d], x3 = gb[3 * XSTR + d];
            ull t;
            t = splat2(x0); ffma2(acc[0][0],t,w0.x); ffma2(acc[0][1],t,w0.y); ffma2(acc[0][2],t,w1.x); ffma2(acc[0][3],t,w1.y);
            t = splat2(x1); ffma2(acc[1][0],t,w0.x); ffma2(acc[1][1],t,w0.y); ffma2(acc[1][2],t,w1.x); ffma2(acc[1][3],t,w1.y);
            t = splat2(x2); ffma2(acc[2][0],t,w0.x); ffma2(acc[2][1],t,w0.y); ffma2(acc[2][2],t,w1.x); ffma2(acc[2][3],t,w1.y);
            t = splat2(x3); ffma2(acc[3][0],t,w0.x); ffma2(acc[3][1],t,w0.y); ffma2(acc[3][2],t,w1.x); ffma2(acc[3][3],t,w1.y);
        }
        const ulonglong2 boA = *reinterpret_cast<const ulonglong2*>(&s->bov[8 * cg]);
        const ulonglong2 boB = *reinterpret_cast<const ulonglong2*>(&s->bov[8 * cg + 4]);
        #pragma unroll
        for (int i = 0; i < 4; ++i) {
            float* op = out + ((size_t)(4 * rg + i) * LRES + l) * 64 + 8 * cg;
            ulonglong2 v0, v1;
            v0.x = add2(acc[i][0], boA.x); v0.y = add2(acc[i][1], boA.y);
            v1.x = add2(acc[i][2], boB.x); v1.y = add2(acc[i][3], boB.y);
            *reinterpret_cast<ulonglong2*>(op)     = v0;
            *reinterpret_cast<ulonglong2*>(op + 4) = v1;
        }
    }
}

extern "C" void kernel_launch(void* const* d_in, const int* in_sizes, int n_in,
                              void* d_out, int out_size) {
    const float* msa = (const float*)d_in[0];
    const float* lnw = (const float*)d_in[1];
    const float* lnb = (const float*)d_in[2];
    const float* wq  = (const float*)d_in[3];
    const float* wk  = (const float*)d_in[4];
    const float* wv  = (const float*)d_in[5];
    const float* wg  = (const float*)d_in[6];
    const float* bg  = (const float*)d_in[7];
    const float* wo  = (const float*)d_in[8];
    const float* bo  = (const float*)d_in[9];
    float* out = (float*)d_out;

    const int smem_bytes = (int)sizeof(Smem);
    cudaFuncSetAttribute(msa_col_attn_v8,
                         cudaFuncAttributeMaxDynamicSharedMemorySize, smem_bytes);
    msa_col_attn_v8<<<LRES, NT, smem_bytes>>>(
        msa, lnw, lnb, wq, wk, wv, wg, bg, wo, bo, out);
}

// round 9
// speedup vs baseline: 1.0550x; 1.0550x over previous
#include <cuda_runtime.h>
#include <math.h>

typedef unsigned long long ull;

namespace {
constexpr int NSEQ = 512;
constexpr int LRES = 1024;
constexpr int NT   = 1024;
constexpr float LN_EPS = 1e-5f;

struct __align__(16) Smem {
    float xg[64 * NSEQ];       // 128 KB: X transposed+swizzled (col-major), then G in place
    float wc[64][80];          // 20 KB: cols 0-63 Wg, 64-71 Wk, 72-79 Wv
    float wo[64 * 64];         // 16 KB (ovec-folded before pass B)
    float kbuf[NSEQ * 8];      // 16 KB: k; later scores[8][512]
    float vT[8 * NSEQ];        // 16 KB
    float lnw[64], lnb[64], bgv[64], bov[64], xsum[64], qvec[64];
    float xpart[16 * 64];      // 4 KB
    float mpart[16], spart[16], opart[16][8], ovec[64];
};  // ~212 KB

__device__ __forceinline__ int swz(int c) { return ((c >> 3) ^ c) & 7; }
__device__ __forceinline__ void ffma2(ull& d_, ull a, ull b) {
    asm("fma.rn.f32x2 %0, %1, %2, %0;" : "+l"(d_) : "l"(a), "l"(b));
}
__device__ __forceinline__ ull splat2(float x) {
    ull r; asm("mov.b64 %0, {%1, %1};" : "=l"(r) : "f"(x)); return r;
}
__device__ __forceinline__ ull add2(ull a, ull b) {
    ull r; asm("add.rn.f32x2 %0, %1, %2;" : "=l"(r) : "l"(a), "l"(b)); return r;
}
__device__ __forceinline__ void unpack2(ull u, float& lo, float& hi) {
    asm("mov.b64 {%0, %1}, %2;" : "=f"(lo), "=f"(hi) : "l"(u));
}
__device__ __forceinline__ float sigmoid_fast(float v) {
    return __fdividef(1.f, 1.f + __expf(-v));
}
} // namespace

__global__ void __launch_bounds__(NT, 1)
msa_col_attn_v9(const float* __restrict__ msa,
                const float* __restrict__ g_lnw, const float* __restrict__ g_lnb,
                const float* __restrict__ g_wq,  const float* __restrict__ g_wk,
                const float* __restrict__ g_wv,  const float* __restrict__ g_wg,
                const float* __restrict__ g_bg,  const float* __restrict__ g_wo,
                const float* __restrict__ g_bo,  float* __restrict__ out)
{
    extern __shared__ float smf[];
    Smem* s = reinterpret_cast<Smem*>(smf);
    const int tid  = threadIdx.x;
    const int l    = blockIdx.x;
    const int lane = tid & 31;
    const int wid  = tid >> 5;

    // ---------------- preamble ----------------
    {
        int d = tid >> 4, c4 = (tid & 15) * 4;
        *reinterpret_cast<float4*>(&s->wc[d][c4]) =
            *reinterpret_cast<const float4*>(g_wg + d * 64 + c4);
        if (tid < 512) {
            int dd = tid >> 3, j = tid & 7;
            s->wc[dd][64 + j] = g_wk[tid];
            s->wc[dd][72 + j] = g_wv[tid];
        }
        ((float4*)s->wo)[tid] = ((const float4*)g_wo)[tid];
        if (tid < 64) {
            s->lnw[tid] = g_lnw[tid];
            s->lnb[tid] = g_lnb[tid];
            s->bgv[tid] = g_bg[tid];
            s->bov[tid] = g_bo[tid];
        }
    }
    __syncthreads();

    // ---------------- LayerNorm: 512x64 -> xg transposed+swizzled ----------------
    // 2 threads per row, 32 features each
    {
        const int lrow  = tid >> 1;     // 0..511
        const int lhalf = tid & 1;      // cols 32*lhalf .. +31
        const float* src = msa + ((size_t)lrow * LRES + l) * 64 + lhalf * 32;
        float4 r[8];
        #pragma unroll
        for (int j = 0; j < 8; ++j) r[j] = ((const float4*)src)[j];

        float sm = 0.f, sq = 0.f;
        #pragma unroll
        for (int j = 0; j < 8; ++j) {
            float4 t = r[j];
            sm += (t.x + t.y) + (t.z + t.w);
            sq  = fmaf(t.x, t.x, fmaf(t.y, t.y, fmaf(t.z, t.z, fmaf(t.w, t.w, sq))));
        }
        sm += __shfl_xor_sync(0xffffffffu, sm, 1);
        sq += __shfl_xor_sync(0xffffffffu, sq, 1);
        float mu   = sm * (1.f / 64.f);
        float var  = sq * (1.f / 64.f) - mu * mu;
        float rstd = rsqrtf(var + LN_EPS);
        float mrs  = -mu * rstd;
        const int rb = lrow >> 2, r0 = lrow & 3;
        #pragma unroll
        for (int j = 0; j < 8; ++j) {
            float4 t = r[j];
            int c0 = lhalf * 32 + 4 * j;
            s->xg[(c0 + 0) * NSEQ + 4 * (rb ^ swz(c0 + 0)) + r0] =
                fmaf(fmaf(t.x, rstd, mrs), s->lnw[c0 + 0], s->lnb[c0 + 0]);
            s->xg[(c0 + 1) * NSEQ + 4 * (rb ^ swz(c0 + 1)) + r0] =
                fmaf(fmaf(t.y, rstd, mrs), s->lnw[c0 + 1], s->lnb[c0 + 1]);
            s->xg[(c0 + 2) * NSEQ + 4 * (rb ^ swz(c0 + 2)) + r0] =
                fmaf(fmaf(t.z, rstd, mrs), s->lnw[c0 + 2], s->lnb[c0 + 2]);
            s->xg[(c0 + 3) * NSEQ + 4 * (rb ^ swz(c0 + 3)) + r0] =
                fmaf(fmaf(t.w, rstd, mrs), s->lnw[c0 + 3], s->lnb[c0 + 3]);
        }
    }
    __syncthreads();

    const int rg = tid >> 3;    // row group: rows 4rg..4rg+3 (0..127)
    const int cg = tid & 7;

    // ---------------- xsum partials (column sums; swizzle permutes rows only) ----------------
    {
        const int c = tid & 63, seg = tid >> 6;     // 16 segs x 32 rows
        const float* colp = s->xg + c * NSEQ;
        const int sw = swz(c);
        float t = 0.f;
        #pragma unroll
        for (int b = 0; b < 8; ++b) {
            const float* p = colp + 4 * ((8 * seg + b) ^ sw);
            t += (p[0] + p[1]) + (p[2] + p[3]);
        }
        s->xpart[seg * 64 + c] = t;
    }

    // ---------------- kv GEMM: 4 rows x 1 col-pair ----------------
    {
        ull ka[4] = {0, 0, 0, 0};
        const float* wb = &s->wc[0][64 + 2 * cg];
        #pragma unroll 8
        for (int d = 0; d < 64; ++d) {
            float4 xv = *reinterpret_cast<const float4*>(&s->xg[d * NSEQ + 4 * (rg ^ swz(d))]);
            ull w2 = *reinterpret_cast<const ull*>(wb + 80 * d);
            ffma2(ka[0], splat2(xv.x), w2);
            ffma2(ka[1], splat2(xv.y), w2);
            ffma2(ka[2], splat2(xv.z), w2);
            ffma2(ka[3], splat2(xv.w), w2);
        }
        if (cg < 4) {
            #pragma unroll
            for (int i = 0; i < 4; ++i)
                *reinterpret_cast<ull*>(&s->kbuf[(4 * rg + i) * 8 + 2 * cg]) = ka[i];
        } else {
            int c0 = 2 * (cg - 4);
            float a[4], b[4];
            #pragma unroll
            for (int i = 0; i < 4; ++i) unpack2(ka[i], a[i], b[i]);
            *reinterpret_cast<float4*>(&s->vT[c0 * NSEQ + 4 * rg])       = make_float4(a[0], a[1], a[2], a[3]);
            *reinterpret_cast<float4*>(&s->vT[(c0 + 1) * NSEQ + 4 * rg]) = make_float4(b[0], b[1], b[2], b[3]);
        }
    }

    // ---------------- gate GEMM: 4 rows x 8 cols ----------------
    ull ga[4][4];
    #pragma unroll
    for (int i = 0; i < 4; ++i)
        #pragma unroll
        for (int p = 0; p < 4; ++p) ga[i][p] = 0;
    {
        const float* wb = &s->wc[0][8 * cg];
        #pragma unroll 4
        for (int d = 0; d < 64; ++d) {
            float4 xv = *reinterpret_cast<const float4*>(&s->xg[d * NSEQ + 4 * (rg ^ swz(d))]);
            ulonglong2 w0 = *reinterpret_cast<const ulonglong2*>(wb + 80 * d);
            ulonglong2 w1 = *reinterpret_cast<const ulonglong2*>(wb + 80 * d + 4);
            ull t;
            t = splat2(xv.x); ffma2(ga[0][0],t,w0.x); ffma2(ga[0][1],t,w0.y); ffma2(ga[0][2],t,w1.x); ffma2(ga[0][3],t,w1.y);
            t = splat2(xv.y); ffma2(ga[1][0],t,w0.x); ffma2(ga[1][1],t,w0.y); ffma2(ga[1][2],t,w1.x); ffma2(ga[1][3],t,w1.y);
            t = splat2(xv.z); ffma2(ga[2][0],t,w0.x); ffma2(ga[2][1],t,w0.y); ffma2(ga[2][2],t,w1.x); ffma2(ga[2][3],t,w1.y);
            t = splat2(xv.w); ffma2(ga[3][0],t,w0.x); ffma2(ga[3][1],t,w0.y); ffma2(ga[3][2],t,w1.x); ffma2(ga[3][3],t,w1.y);
        }
    }
    __syncthreads();   // all xg reads + xpart writes done

    // xsum reduce
    if (tid < 64) {
        float t = 0.f;
        #pragma unroll
        for (int w = 0; w < 16; ++w) t += s->xpart[w * 64 + tid];
        s->xsum[tid] = t;
    }

    // ---------------- gate epilogue: G = sigmoid(P + bg) -> xg in place ----------------
    {
        #pragma unroll
        for (int c = 0; c < 8; ++c) {
            int col = 8 * cg + c;
            float bgc = s->bgv[col];
            float g[4];
            #pragma unroll
            for (int i = 0; i < 4; ++i) {
                float lo, hi;
                unpack2(ga[i][c >> 1], lo, hi);
                g[i] = sigmoid_fast(((c & 1) ? hi : lo) + bgc);
            }
            *reinterpret_cast<float4*>(&s->xg[col * NSEQ + 4 * (rg ^ swz(col))]) =
                make_float4(g[0], g[1], g[2], g[3]);
        }
    }
    __syncthreads();   // xsum visible; G writes done

    // qvec partials
    {
        int dg = tid >> 6, c = tid & 63;
        float p = 0.f;
        #pragma unroll
        for (int i = 0; i < 4; ++i)
            p = fmaf(s->xsum[4 * dg + i], g_wq[(4 * dg + i) * 64 + c], p);
        s->xpart[dg * 64 + c] = p;
    }
    __syncthreads();

    // qvec reduce + k into regs (kbuf overlaid next)
    if (tid < 64) {
        float q = 0.f;
        #pragma unroll
        for (int dg = 0; dg < 16; ++dg) q += s->xpart[dg * 64 + tid];
        s->qvec[tid] = q * (float)(0.35355339059327373 / 512.0); // (1/sqrt(8))/N
    }
    const int sn = tid & 511, hh = tid >> 9;
    float4 k0 = *reinterpret_cast<const float4*>(&s->kbuf[sn * 8]);
    float4 k1 = *reinterpret_cast<const float4*>(&s->kbuf[sn * 8 + 4]);
    __syncthreads();

    // ---------------- scores (overlay kbuf): 4 heads per thread ----------------
    {
        #pragma unroll
        for (int j = 0; j < 4; ++j) {
            int h = 4 * hh + j;
            const float* qf = &s->qvec[8 * h];
            float v = qf[0]*k0.x + qf[1]*k0.y + qf[2]*k0.z + qf[3]*k0.w
                    + qf[4]*k1.x + qf[5]*k1.y + qf[6]*k1.z + qf[7]*k1.w;
            s->kbuf[h * 512 + sn] = v;
        }
    }
    __syncthreads();

    // ---------------- softmax partials: 2 warps per head ----------------
    if (wid < 16) {
        int h = wid >> 1, half = wid & 1;
        const float* sc = s->kbuf + h * 512 + half * 256;
        float sv[8], m = -1e30f;
        #pragma unroll
        for (int k = 0; k < 8; ++k) { sv[k] = sc[lane + 32 * k]; m = fmaxf(m, sv[k]); }
        #pragma unroll
        for (int off = 16; off > 0; off >>= 1)
            m = fmaxf(m, __shfl_xor_sync(0xffffffffu, m, off));
        float ssum = 0.f, acc[8];
        #pragma unroll
        for (int d = 0; d < 8; ++d) acc[d] = 0.f;
        #pragma unroll
        for (int k = 0; k < 8; ++k) {
            float e = __expf(sv[k] - m);
            ssum += e;
            int n = half * 256 + lane + 32 * k;
            #pragma unroll
            for (int d = 0; d < 8; ++d) acc[d] = fmaf(e, s->vT[d * NSEQ + n], acc[d]);
        }
        #pragma unroll
        for (int off = 16; off > 0; off >>= 1) {
            ssum += __shfl_xor_sync(0xffffffffu, ssum, off);
            #pragma unroll
            for (int d = 0; d < 8; ++d) acc[d] += __shfl_xor_sync(0xffffffffu, acc[d], off);
        }
        if (lane == 0) {
            s->mpart[wid] = m;
            s->spart[wid] = ssum;
            #pragma unroll
            for (int d = 0; d < 8; ++d) s->opart[wid][d] = acc[d];
        }
    }
    __syncthreads();

    // ovec combine (exact two-way softmax merge)
    if (tid < 64) {
        int h = tid >> 3, d = tid & 7;
        float m0 = s->mpart[2 * h], m1 = s->mpart[2 * h + 1];
        float m = fmaxf(m0, m1);
        float e0 = __expf(m0 - m), e1 = __expf(m1 - m);
        float ss = s->spart[2 * h] * e0 + s->spart[2 * h + 1] * e1;
        float ov = s->opart[2 * h][d] * e0 + s->opart[2 * h + 1][d] * e1;
        s->ovec[8 * h + d] = ov / ss;
    }
    __syncthreads();

    // fold ovec into Wo rows
    {
        float4 w4 = ((float4*)s->wo)[tid];
        float ov = s->ovec[tid >> 4];
        w4.x *= ov; w4.y *= ov; w4.z *= ov; w4.w *= ov;
        ((float4*)s->wo)[tid] = w4;
    }
    __syncthreads();

    // ---------------- pass B: out = G @ Wo' + bo ----------------
    {
        ull acc[4][4];
        #pragma unroll
        for (int i = 0; i < 4; ++i)
            #pragma unroll
            for (int p = 0; p < 4; ++p) acc[i][p] = 0;
        const float* wb = s->wo + 8 * cg;
        #pragma unroll 4
        for (int d = 0; d < 64; ++d) {
            float4 xv = *reinterpret_cast<const float4*>(&s->xg[d * NSEQ + 4 * (rg ^ swz(d))]);
            ulonglong2 w0 = *reinterpret_cast<const ulonglong2*>(wb + 64 * d);
            ulonglong2 w1 = *reinterpret_cast<const ulonglong2*>(wb + 64 * d + 4);
            ull t;
            t = splat2(xv.x); ffma2(acc[0][0],t,w0.x); ffma2(acc[0][1],t,w0.y); ffma2(acc[0][2],t,w1.x); ffma2(acc[0][3],t,w1.y);
            t = splat2(xv.y); ffma2(acc[1][0],t,w0.x); ffma2(acc[1][1],t,w0.y); ffma2(acc[1][2],t,w1.x); ffma2(acc[1][3],t,w1.y);
            t = splat2(xv.z); ffma2(acc[2][0],t,w0.x); ffma2(acc[2][1],t,w0.y); ffma2(acc[2][2],t,w1.x); ffma2(acc[2][3],t,w1.y);
            t = splat2(xv.w); ffma2(acc[3][0],t,w0.x); ffma2(acc[3][1],t,w0.y); ffma2(acc[3][2],t,w1.x); ffma2(acc[3][3],t,w1.y);
        }
        const ulonglong2 boA = *reinterpret_cast<const ulonglong2*>(&s->bov[8 * cg]);
        const ulonglong2 boB = *reinterpret_cast<const ulonglong2*>(&s->bov[8 * cg + 4]);
        #pragma unroll
        for (int i = 0; i < 4; ++i) {
            float* op = out + ((size_t)(4 * rg + i) * LRES + l) * 64 + 8 * cg;
            ulonglong2 v0, v1;
            v0.x = add2(acc[i][0], boA.x); v0.y = add2(acc[i][1], boA.y);
            v1.x = add2(acc[i][2], boB.x); v1.y = add2(acc[i][3], boB.y);
            *reinterpret_cast<ulonglong2*>(op)     = v0;
            *reinterpret_cast<ulonglong2*>(op + 4) = v1;
        }
    }
}

extern "C" void kernel_launch(void* const* d_in, const int* in_sizes, int n_in,
                              void* d_out, int out_size) {
    const float* msa = (const float*)d_in[0];
    const float* lnw = (const float*)d_in[1];
    const float* lnb = (const float*)d_in[2];
    const float* wq  = (const float*)d_in[3];
    const float* wk  = (const float*)d_in[4];
    const float* wv  = (const float*)d_in[5];
    const float* wg  = (const float*)d_in[6];
    const float* bg  = (const float*)d_in[7];
    const float* wo  = (const float*)d_in[8];
    const float* bo  = (const float*)d_in[9];
    float* out = (float*)d_out;

    const int smem_bytes = (int)sizeof(Smem);
    cudaFuncSetAttribute(msa_col_attn_v9,
                         cudaFuncAttributeMaxDynamicSharedMemorySize, smem_bytes);
    msa_col_attn_v9<<<LRES, NT, smem_bytes>>>(
        msa, lnw, lnb, wq, wk, wv, wg, bg, wo, bo, out);
}

// round 10
// speedup vs baseline: 1.6958x; 1.6074x over previous
#include <cuda_runtime.h>
#include <math.h>

typedef unsigned long long ull;

namespace {
constexpr int NSEQ = 512;
constexpr int LRES = 1024;
constexpr int NT   = 512;
constexpr float LN_EPS = 1e-5f;

struct __align__(16) Smem {
    float xg[64 * NSEQ];       // 128 KB: X transposed+swizzled, then G in place
    float wc[64][80];          // 20 KB: cols 0-63 Wg, 64-71 Wk, 72-79 Wv
    float wo[64 * 64];         // 16 KB (ovec-folded before pass B)
    float kbuf[NSEQ][8];       // 16 KB
    float vT[8 * NSEQ];        // 16 KB
    float scores[8 * NSEQ];    // 16 KB
    float lnw[64], lnb[64], bgv[64], bov[64], xsum[64], qvec[64], ovec[64];
    float xpart[16 * 64];      // 4 KB
    float mpart[16], spart[16], opart[16][8];
};

__device__ __forceinline__ int swz(int c) { return ((c >> 3) ^ c) & 7; }
__device__ __forceinline__ void ffma2(ull& d_, ull a, ull b) {
    asm("fma.rn.f32x2 %0, %1, %2, %0;" : "+l"(d_) : "l"(a), "l"(b));
}
__device__ __forceinline__ ull splat2(float x) {
    ull r; asm("mov.b64 %0, {%1, %1};" : "=l"(r) : "f"(x)); return r;
}
__device__ __forceinline__ ull add2(ull a, ull b) {
    ull r; asm("add.rn.f32x2 %0, %1, %2;" : "=l"(r) : "l"(a), "l"(b)); return r;
}
__device__ __forceinline__ void unpack2(ull u, float& lo, float& hi) {
    asm("mov.b64 {%0, %1}, %2;" : "=f"(lo), "=f"(hi) : "l"(u));
}
// sigmoid(x) = 0.5*tanh(x/2) + 0.5  (single MUFU)
__device__ __forceinline__ float sigmoid_t(float v) {
    float t; asm("tanh.approx.f32 %0, %1;" : "=f"(t) : "f"(v * 0.5f));
    return fmaf(t, 0.5f, 0.5f);
}
} // namespace

__global__ void __launch_bounds__(NT, 1)
msa_col_attn_v10(const float* __restrict__ msa,
                 const float* __restrict__ g_lnw, const float* __restrict__ g_lnb,
                 const float* __restrict__ g_wq,  const float* __restrict__ g_wk,
                 const float* __restrict__ g_wv,  const float* __restrict__ g_wg,
                 const float* __restrict__ g_bg,  const float* __restrict__ g_wo,
                 const float* __restrict__ g_bo,  float* __restrict__ out)
{
    extern __shared__ float smf[];
    Smem* s = reinterpret_cast<Smem*>(smf);
    const int tid  = threadIdx.x;
    const int l    = blockIdx.x;
    const int lane = tid & 31;
    const int wid  = tid >> 5;

    // ---------------- preamble: weights to SMEM ----------------
    #pragma unroll
    for (int i = 0; i < 8; ++i) {
        int idx = tid + i * NT;
        s->wc[idx >> 6][idx & 63] = g_wg[idx];
    }
    {   // Wk/Wv: exactly 512 elements each, one pass
        int d = tid >> 3, j = tid & 7;
        s->wc[d][64 + j] = g_wk[tid];
        s->wc[d][72 + j] = g_wv[tid];
    }
    #pragma unroll
    for (int i = 0; i < 2; ++i) {
        int idx = tid + i * NT;
        ((float4*)s->wo)[idx] = ((const float4*)g_wo)[idx];
    }
    if (tid < 64) {
        s->lnw[tid] = g_lnw[tid];
        s->lnb[tid] = g_lnb[tid];
        s->bgv[tid] = g_bg[tid];
        s->bov[tid] = g_bo[tid];
    }
    // wq in registers: thread (dg=tid>>6, c=tid&63) holds wq[8dg+i][c]
    float wqr[8];
    {
        int dg = tid >> 6, c = tid & 63;
        #pragma unroll
        for (int i = 0; i < 8; ++i) wqr[i] = g_wq[(8 * dg + i) * 64 + c];
    }
    __syncthreads();

    // ---------------- LayerNorm: 512x64 -> xg transposed+swizzled ----------------
    // warp covers 2 rows/iter; 16 lanes span one 256B row; prefetch depth 4
    {
        const int lq4 = lane & 15;
        const int lh  = lane >> 4;
        const size_t step = (size_t)32 * LRES * 64;
        const float* base = msa + ((size_t)(wid * 2 + lh) * LRES + l) * 64 + lq4 * 4;
        float xacc0 = 0.f, xacc1 = 0.f, xacc2 = 0.f, xacc3 = 0.f;
        float4 buf[4];
        #pragma unroll
        for (int j = 0; j < 4; ++j)
            buf[j] = *reinterpret_cast<const float4*>(base + (size_t)j * step);
        #pragma unroll 4
        for (int it = 0; it < 16; ++it) {
            float4 cur = buf[it & 3];
            if (it + 4 < 16)
                buf[it & 3] = *reinterpret_cast<const float4*>(base + (size_t)(it + 4) * step);
            float sm = (cur.x + cur.y) + (cur.z + cur.w);
            float sq = fmaf(cur.x, cur.x, fmaf(cur.y, cur.y,
                       fmaf(cur.z, cur.z, cur.w * cur.w)));
            #pragma unroll
            for (int off = 1; off < 16; off <<= 1) {
                sm += __shfl_xor_sync(0xffffffffu, sm, off);
                sq += __shfl_xor_sync(0xffffffffu, sq, off);
            }
            float mu   = sm * (1.f / 64.f);
            float var  = sq * (1.f / 64.f) - mu * mu;
            float rstd = rsqrtf(var + LN_EPS);
            float mrs  = -mu * rstd;
            int row = it * 32 + wid * 2 + lh;
            int rb = row >> 2, r0 = row & 3;
            int c0 = 4 * lq4;
            float v0 = fmaf(fmaf(cur.x, rstd, mrs), s->lnw[c0 + 0], s->lnb[c0 + 0]);
            float v1 = fmaf(fmaf(cur.y, rstd, mrs), s->lnw[c0 + 1], s->lnb[c0 + 1]);
            float v2 = fmaf(fmaf(cur.z, rstd, mrs), s->lnw[c0 + 2], s->lnb[c0 + 2]);
            float v3 = fmaf(fmaf(cur.w, rstd, mrs), s->lnw[c0 + 3], s->lnb[c0 + 3]);
            s->xg[(c0 + 0) * NSEQ + 4 * (rb ^ swz(c0 + 0)) + r0] = v0;
            s->xg[(c0 + 1) * NSEQ + 4 * (rb ^ swz(c0 + 1)) + r0] = v1;
            s->xg[(c0 + 2) * NSEQ + 4 * (rb ^ swz(c0 + 2)) + r0] = v2;
            s->xg[(c0 + 3) * NSEQ + 4 * (rb ^ swz(c0 + 3)) + r0] = v3;
            xacc0 += v0; xacc1 += v1; xacc2 += v2; xacc3 += v3;
        }
        xacc0 += __shfl_xor_sync(0xffffffffu, xacc0, 16);
        xacc1 += __shfl_xor_sync(0xffffffffu, xacc1, 16);
        xacc2 += __shfl_xor_sync(0xffffffffu, xacc2, 16);
        xacc3 += __shfl_xor_sync(0xffffffffu, xacc3, 16);
        if (lane < 16) {
            float* xp = s->xpart + wid * 64 + 4 * lq4;
            xp[0] = xacc0; xp[1] = xacc1; xp[2] = xacc2; xp[3] = xacc3;
        }
    }
    __syncthreads();

    // xsum (consumed after the next barrier)
    if (tid < 64) {
        float t = 0.f;
        #pragma unroll
        for (int w = 0; w < 16; ++w) t += s->xpart[w * 64 + tid];
        s->xsum[tid] = t;
    }

    // ---------------- pass A: gate GEMM (8 rows x 8 cols per thread) ----------------
    const int rg = tid >> 3;   // rows 8rg..8rg+7
    const int cg = tid & 7;    // cols 8cg..8cg+7
    ull ga[8][4];
    #pragma unroll
    for (int r = 0; r < 8; ++r)
        #pragma unroll
        for (int p = 0; p < 4; ++p) ga[r][p] = 0;

    #pragma unroll 4
    for (int d = 0; d < 64; ++d) {
        const float* xp = &s->xg[d * NSEQ];
        float4 xa = *reinterpret_cast<const float4*>(xp + 4 * ((2 * rg) ^ swz(d)));
        float4 xb = *reinterpret_cast<const float4*>(xp + 4 * ((2 * rg + 1) ^ swz(d)));
        ulonglong2 w0 = *reinterpret_cast<const ulonglong2*>(&s->wc[d][8 * cg]);
        ulonglong2 w1 = *reinterpret_cast<const ulonglong2*>(&s->wc[d][8 * cg + 4]);
        ull t;
        t = splat2(xa.x); ffma2(ga[0][0],t,w0.x); ffma2(ga[0][1],t,w0.y); ffma2(ga[0][2],t,w1.x); ffma2(ga[0][3],t,w1.y);
        t = splat2(xa.y); ffma2(ga[1][0],t,w0.x); ffma2(ga[1][1],t,w0.y); ffma2(ga[1][2],t,w1.x); ffma2(ga[1][3],t,w1.y);
        t = splat2(xa.z); ffma2(ga[2][0],t,w0.x); ffma2(ga[2][1],t,w0.y); ffma2(ga[2][2],t,w1.x); ffma2(ga[2][3],t,w1.y);
        t = splat2(xa.w); ffma2(ga[3][0],t,w0.x); ffma2(ga[3][1],t,w0.y); ffma2(ga[3][2],t,w1.x); ffma2(ga[3][3],t,w1.y);
        t = splat2(xb.x); ffma2(ga[4][0],t,w0.x); ffma2(ga[4][1],t,w0.y); ffma2(ga[4][2],t,w1.x); ffma2(ga[4][3],t,w1.y);
        t = splat2(xb.y); ffma2(ga[5][0],t,w0.x); ffma2(ga[5][1],t,w0.y); ffma2(ga[5][2],t,w1.x); ffma2(ga[5][3],t,w1.y);
        t = splat2(xb.z); ffma2(ga[6][0],t,w0.x); ffma2(ga[6][1],t,w0.y); ffma2(ga[6][2],t,w1.x); ffma2(ga[6][3],t,w1.y);
        t = splat2(xb.w); ffma2(ga[7][0],t,w0.x); ffma2(ga[7][1],t,w0.y); ffma2(ga[7][2],t,w1.x); ffma2(ga[7][3],t,w1.y);
    }

    // ---------------- pass A: kv GEMM (8 rows x 2 cols, row-pair packed) ----------------
    ull ka[4][2];
    #pragma unroll
    for (int p = 0; p < 4; ++p) { ka[p][0] = 0; ka[p][1] = 0; }
    #pragma unroll 8
    for (int d = 0; d < 64; ++d) {
        const float* xp = &s->xg[d * NSEQ];
        ulonglong2 xa = *reinterpret_cast<const ulonglong2*>(xp + 4 * ((2 * rg) ^ swz(d)));
        ulonglong2 xb = *reinterpret_cast<const ulonglong2*>(xp + 4 * ((2 * rg + 1) ^ swz(d)));
        float2 wk = *reinterpret_cast<const float2*>(&s->wc[d][64 + 2 * cg]);
        ull w0 = splat2(wk.x), w1 = splat2(wk.y);
        ffma2(ka[0][0], xa.x, w0); ffma2(ka[0][1], xa.x, w1);
        ffma2(ka[1][0], xa.y, w0); ffma2(ka[1][1], xa.y, w1);
        ffma2(ka[2][0], xb.x, w0); ffma2(ka[2][1], xb.x, w1);
        ffma2(ka[3][0], xb.y, w0); ffma2(ka[3][1], xb.y, w1);
    }
    __syncthreads();   // all xg reads done; safe to overwrite with G

    // gate epilogue: G = sigmoid(P + bg) -> xg (same layout)
    #pragma unroll
    for (int c = 0; c < 8; ++c) {
        int col = 8 * cg + c;
        float bgc = s->bgv[col];
        float g[8];
        #pragma unroll
        for (int r = 0; r < 8; ++r) {
            float lo, hi;
            unpack2(ga[r][c >> 1], lo, hi);
            float v = (c & 1) ? hi : lo;
            g[r] = sigmoid_t(v + bgc);
        }
        float* dst = &s->xg[col * NSEQ];
        *reinterpret_cast<float4*>(dst + 4 * ((2 * rg) ^ swz(col)))     = make_float4(g[0], g[1], g[2], g[3]);
        *reinterpret_cast<float4*>(dst + 4 * ((2 * rg + 1) ^ swz(col))) = make_float4(g[4], g[5], g[6], g[7]);
    }
    // kv epilogue
    if (cg < 4) {
        #pragma unroll
        for (int p = 0; p < 4; ++p) {
            float a0, a1, b0, b1;
            unpack2(ka[p][0], a0, a1);
            unpack2(ka[p][1], b0, b1);
            s->kbuf[8 * rg + 2 * p    ][2 * cg]     = a0;
            s->kbuf[8 * rg + 2 * p    ][2 * cg + 1] = b0;
            s->kbuf[8 * rg + 2 * p + 1][2 * cg]     = a1;
            s->kbuf[8 * rg + 2 * p + 1][2 * cg + 1] = b1;
        }
    } else {
        int c0 = 2 * cg - 8;
        float a[8], b[8];
        #pragma unroll
        for (int p = 0; p < 4; ++p) {
            unpack2(ka[p][0], a[2 * p], a[2 * p + 1]);
            unpack2(ka[p][1], b[2 * p], b[2 * p + 1]);
        }
        *reinterpret_cast<float4*>(&s->vT[c0 * NSEQ + 8 * rg])           = make_float4(a[0], a[1], a[2], a[3]);
        *reinterpret_cast<float4*>(&s->vT[c0 * NSEQ + 8 * rg + 4])       = make_float4(a[4], a[5], a[6], a[7]);
        *reinterpret_cast<float4*>(&s->vT[(c0 + 1) * NSEQ + 8 * rg])     = make_float4(b[0], b[1], b[2], b[3]);
        *reinterpret_cast<float4*>(&s->vT[(c0 + 1) * NSEQ + 8 * rg + 4]) = make_float4(b[4], b[5], b[6], b[7]);
    }
    // qvec partials (xsum written before previous barrier)
    {
        int dg = tid >> 6, c = tid & 63;
        float p = 0.f;
        #pragma unroll
        for (int i = 0; i < 8; ++i) p = fmaf(s->xsum[8 * dg + i], wqr[i], p);
        s->xpart[dg * 64 + c] = p;
    }
    __syncthreads();

    if (tid < 64) {
        float q = 0.f;
        #pragma unroll
        for (int dg = 0; dg < 8; ++dg) q += s->xpart[dg * 64 + tid];
        s->qvec[tid] = q * (float)(0.35355339059327373 / 512.0); // (1/sqrt(8))/N
    }
    __syncthreads();

    // ---------------- scores[h][n] ----------------
    {
        float4 k0 = *reinterpret_cast<const float4*>(&s->kbuf[tid][0]);
        float4 k1 = *reinterpret_cast<const float4*>(&s->kbuf[tid][4]);
        #pragma unroll
        for (int h = 0; h < 8; ++h) {
            const float* qf = &s->qvec[h * 8];
            float sc = qf[0]*k0.x + qf[1]*k0.y + qf[2]*k0.z + qf[3]*k0.w
                     + qf[4]*k1.x + qf[5]*k1.y + qf[6]*k1.z + qf[7]*k1.w;
            s->scores[h * NSEQ + tid] = sc;
        }
    }
    __syncthreads();

    // ---------------- softmax partials: 2 warps per head ----------------
    {
        int h = wid >> 1, half = wid & 1;
        const float* sc = s->scores + h * NSEQ + half * 256;
        float sv[8], m = -1e30f;
        #pragma unroll
        for (int k = 0; k < 8; ++k) { sv[k] = sc[lane + 32 * k]; m = fmaxf(m, sv[k]); }
        #pragma unroll
        for (int off = 16; off > 0; off >>= 1)
            m = fmaxf(m, __shfl_xor_sync(0xffffffffu, m, off));
        float ssum = 0.f, acc[8];
        #pragma unroll
        for (int d = 0; d < 8; ++d) acc[d] = 0.f;
        #pragma unroll
        for (int k = 0; k < 8; ++k) {
            float e = __expf(sv[k] - m);
            ssum += e;
            int n = half * 256 + lane + 32 * k;
            #pragma unroll
            for (int d = 0; d < 8; ++d) acc[d] = fmaf(e, s->vT[d * NSEQ + n], acc[d]);
        }
        #pragma unroll
        for (int off = 16; off > 0; off >>= 1) {
            ssum += __shfl_xor_sync(0xffffffffu, ssum, off);
            #pragma unroll
            for (int d = 0; d < 8; ++d) acc[d] += __shfl_xor_sync(0xffffffffu, acc[d], off);
        }
        if (lane == 0) {
            s->mpart[wid] = m;
            s->spart[wid] = ssum;
            #pragma unroll
            for (int d = 0; d < 8; ++d) s->opart[wid][d] = acc[d];
        }
    }
    __syncthreads();

    // ovec combine (exact two-way softmax merge)
    if (tid < 64) {
        int h = tid >> 3, d = tid & 7;
        float m0 = s->mpart[2 * h], m1 = s->mpart[2 * h + 1];
        float m = fmaxf(m0, m1);
        float e0 = __expf(m0 - m), e1 = __expf(m1 - m);
        float ss = s->spart[2 * h] * e0 + s->spart[2 * h + 1] * e1;
        float ov = s->opart[2 * h][d] * e0 + s->opart[2 * h + 1][d] * e1;
        s->ovec[8 * h + d] = ov / ss;
    }
    __syncthreads();

    // fold ovec into Wo rows
    #pragma unroll
    for (int i = 0; i < 2; ++i) {
        int idx = tid + i * NT;
        float4 w4 = ((float4*)s->wo)[idx];
        float ov = s->ovec[idx >> 4];
        w4.x *= ov; w4.y *= ov; w4.z *= ov; w4.w *= ov;
        ((float4*)s->wo)[idx] = w4;
    }
    __syncthreads();

    // ---------------- pass B: out = G @ Wo' + bo ----------------
    {
        ull acc[8][4];
        #pragma unroll
        for (int i = 0; i < 8; ++i)
            #pragma unroll
            for (int p = 0; p < 4; ++p) acc[i][p] = 0;

        #pragma unroll 4
        for (int d = 0; d < 64; ++d) {
            const float* gp = &s->xg[d * NSEQ];
            float4 xa = *reinterpret_cast<const float4*>(gp + 4 * ((2 * rg) ^ swz(d)));
            float4 xb = *reinterpret_cast<const float4*>(gp + 4 * ((2 * rg + 1) ^ swz(d)));
            ulonglong2 wA = *reinterpret_cast<const ulonglong2*>(&s->wo[d * 64 + 8 * cg]);
            ulonglong2 wB = *reinterpret_cast<const ulonglong2*>(&s->wo[d * 64 + 8 * cg + 4]);
            ull t;
            t = splat2(xa.x); ffma2(acc[0][0],t,wA.x); ffma2(acc[0][1],t,wA.y); ffma2(acc[0][2],t,wB.x); ffma2(acc[0][3],t,wB.y);
            t = splat2(xa.y); ffma2(acc[1][0],t,wA.x); ffma2(acc[1][1],t,wA.y); ffma2(acc[1][2],t,wB.x); ffma2(acc[1][3],t,wB.y);
            t = splat2(xa.z); ffma2(acc[2][0],t,wA.x); ffma2(acc[2][1],t,wA.y); ffma2(acc[2][2],t,wB.x); ffma2(acc[2][3],t,wB.y);
            t = splat2(xa.w); ffma2(acc[3][0],t,wA.x); ffma2(acc[3][1],t,wA.y); ffma2(acc[3][2],t,wB.x); ffma2(acc[3][3],t,wB.y);
            t = splat2(xb.x); ffma2(acc[4][0],t,wA.x); ffma2(acc[4][1],t,wA.y); ffma2(acc[4][2],t,wB.x); ffma2(acc[4][3],t,wB.y);
            t = splat2(xb.y); ffma2(acc[5][0],t,wA.x); ffma2(acc[5][1],t,wA.y); ffma2(acc[5][2],t,wB.x); ffma2(acc[5][3],t,wB.y);
            t = splat2(xb.z); ffma2(acc[6][0],t,wA.x); ffma2(acc[6][1],t,wA.y); ffma2(acc[6][2],t,wB.x); ffma2(acc[6][3],t,wB.y);
            t = splat2(xb.w); ffma2(acc[7][0],t,wA.x); ffma2(acc[7][1],t,wA.y); ffma2(acc[7][2],t,wB.x); ffma2(acc[7][3],t,wB.y);
        }

        const ulonglong2 boA = *reinterpret_cast<const ulonglong2*>(&s->bov[8 * cg]);
        const ulonglong2 boB = *reinterpret_cast<const ulonglong2*>(&s->bov[8 * cg + 4]);
        #pragma unroll
        for (int i = 0; i < 8; ++i) {
            size_t row = (size_t)(8 * rg + i);
            float* op = out + (row * LRES + l) * 64 + 8 * cg;
            ulonglong2 v0, v1;
            v0.x = add2(acc[i][0], boA.x); v0.y = add2(acc[i][1], boA.y);
            v1.x = add2(acc[i][2], boB.x); v1.y = add2(acc[i][3], boB.y);
            *reinterpret_cast<ulonglong2*>(op)     = v0;
            *reinterpret_cast<ulonglong2*>(op + 4) = v1;
        }
    }
}

extern "C" void kernel_launch(void* const* d_in, const int* in_sizes, int n_in,
                              void* d_out, int out_size) {
    const float* msa = (const float*)d_in[0];
    const float* lnw = (const float*)d_in[1];
    const float* lnb = (const float*)d_in[2];
    const float* wq  = (const float*)d_in[3];
    const float* wk  = (const float*)d_in[4];
    const float* wv  = (const float*)d_in[5];
    const float* wg  = (const float*)d_in[6];
    const float* bg  = (const float*)d_in[7];
    const float* wo  = (const float*)d_in[8];
    const float* bo  = (const float*)d_in[9];
    float* out = (float*)d_out;

    const int smem_bytes = (int)sizeof(Smem);
    cudaFuncSetAttribute(msa_col_attn_v10,
                         cudaFuncAttributeMaxDynamicSharedMemorySize, smem_bytes);
    msa_col_attn_v10<<<LRES, NT, smem_bytes>>>(
        msa, lnw, lnb, wq, wk, wv, wg, bg, wo, bo, out);
}

// round 11
// speedup vs baseline: 1.7805x; 1.0499x over previous
#include <cuda_runtime.h>
#include <math.h>

typedef unsigned long long ull;

namespace {
constexpr int NSEQ = 512;
constexpr int LRES = 1024;
constexpr int NT   = 512;
constexpr float LN_EPS = 1e-5f;

struct __align__(16) Smem {
    float xg[64 * NSEQ];       // 128 KB: X transposed+swizzled, then G in place
    float wc[64][80];          // 20 KB: cols 0-63 Wg, 64-71 Wk, 72-79 Wv
    float wo[64 * 64];         // 16 KB (ovec-folded before pass B)
    float kbuf[NSEQ][8];       // 16 KB
    float vT[8 * NSEQ];        // 16 KB
    float scores[8 * NSEQ];    // 16 KB
    float lnw[64], lnb[64], bgv[64], bov[64], xsum[64], qvec[64], ovec[64];
    float xpart[16 * 64];      // 4 KB
    float mpart[16], spart[16], opart[16][8];
};

__device__ __forceinline__ int swz(int c) { return ((c >> 3) ^ c) & 7; }
__device__ __forceinline__ void ffma2(ull& d_, ull a, ull b) {
    asm("fma.rn.f32x2 %0, %1, %2, %0;" : "+l"(d_) : "l"(a), "l"(b));
}
__device__ __forceinline__ ull splat2(float x) {
    ull r; asm("mov.b64 %0, {%1, %1};" : "=l"(r) : "f"(x)); return r;
}
__device__ __forceinline__ ull add2(ull a, ull b) {
    ull r; asm("add.rn.f32x2 %0, %1, %2;" : "=l"(r) : "l"(a), "l"(b)); return r;
}
__device__ __forceinline__ void unpack2(ull u, float& lo, float& hi) {
    asm("mov.b64 {%0, %1}, %2;" : "=f"(lo), "=f"(hi) : "l"(u));
}
// sigmoid(x) = 0.5*tanh(x/2) + 0.5  (single MUFU)
__device__ __forceinline__ float sigmoid_t(float v) {
    float t; asm("tanh.approx.f32 %0, %1;" : "=f"(t) : "f"(v * 0.5f));
    return fmaf(t, 0.5f, 0.5f);
}
} // namespace

__global__ void __launch_bounds__(NT, 1)
msa_col_attn_v11(const float* __restrict__ msa,
                 const float* __restrict__ g_lnw, const float* __restrict__ g_lnb,
                 const float* __restrict__ g_wq,  const float* __restrict__ g_wk,
                 const float* __restrict__ g_wv,  const float* __restrict__ g_wg,
                 const float* __restrict__ g_bg,  const float* __restrict__ g_wo,
                 const float* __restrict__ g_bo,  float* __restrict__ out)
{
    extern __shared__ float smf[];
    Smem* s = reinterpret_cast<Smem*>(smf);
    const int tid  = threadIdx.x;
    const int l    = blockIdx.x;
    const int lane = tid & 31;
    const int wid  = tid >> 5;

    // ---------------- preamble: weights to SMEM ----------------
    #pragma unroll
    for (int i = 0; i < 8; ++i) {
        int idx = tid + i * NT;
        s->wc[idx >> 6][idx & 63] = g_wg[idx];
    }
    {   // Wk/Wv: exactly 512 elements each, one pass
        int d = tid >> 3, j = tid & 7;
        s->wc[d][64 + j] = g_wk[tid];
        s->wc[d][72 + j] = g_wv[tid];
    }
    #pragma unroll
    for (int i = 0; i < 2; ++i) {
        int idx = tid + i * NT;
        ((float4*)s->wo)[idx] = ((const float4*)g_wo)[idx];
    }
    if (tid < 64) {
        s->lnw[tid] = g_lnw[tid];
        s->lnb[tid] = g_lnb[tid];
        s->bgv[tid] = g_bg[tid];
        s->bov[tid] = g_bo[tid];
    }
    // wq in registers
    float wqr[8];
    {
        int dg = tid >> 6, c = tid & 63;
        #pragma unroll
        for (int i = 0; i < 8; ++i) wqr[i] = g_wq[(8 * dg + i) * 64 + c];
    }
    __syncthreads();

    // ---------------- LayerNorm: 512x64 -> xg transposed+swizzled (prefetch 4) ----------------
    {
        const int lq4 = lane & 15;
        const int lh  = lane >> 4;
        const size_t step = (size_t)32 * LRES * 64;
        const float* base = msa + ((size_t)(wid * 2 + lh) * LRES + l) * 64 + lq4 * 4;
        float xacc0 = 0.f, xacc1 = 0.f, xacc2 = 0.f, xacc3 = 0.f;
        float4 buf[4];
        #pragma unroll
        for (int j = 0; j < 4; ++j)
            buf[j] = *reinterpret_cast<const float4*>(base + (size_t)j * step);
        #pragma unroll 4
        for (int it = 0; it < 16; ++it) {
            float4 cur = buf[it & 3];
            if (it + 4 < 16)
                buf[it & 3] = *reinterpret_cast<const float4*>(base + (size_t)(it + 4) * step);
            float sm = (cur.x + cur.y) + (cur.z + cur.w);
            float sq = fmaf(cur.x, cur.x, fmaf(cur.y, cur.y,
                       fmaf(cur.z, cur.z, cur.w * cur.w)));
            #pragma unroll
            for (int off = 1; off < 16; off <<= 1) {
                sm += __shfl_xor_sync(0xffffffffu, sm, off);
                sq += __shfl_xor_sync(0xffffffffu, sq, off);
            }
            float mu   = sm * (1.f / 64.f);
            float var  = sq * (1.f / 64.f) - mu * mu;
            float rstd = rsqrtf(var + LN_EPS);
            float mrs  = -mu * rstd;
            int row = it * 32 + wid * 2 + lh;
            int rb = row >> 2, r0 = row & 3;
            int c0 = 4 * lq4;
            float v0 = fmaf(fmaf(cur.x, rstd, mrs), s->lnw[c0 + 0], s->lnb[c0 + 0]);
            float v1 = fmaf(fmaf(cur.y, rstd, mrs), s->lnw[c0 + 1], s->lnb[c0 + 1]);
            float v2 = fmaf(fmaf(cur.z, rstd, mrs), s->lnw[c0 + 2], s->lnb[c0 + 2]);
            float v3 = fmaf(fmaf(cur.w, rstd, mrs), s->lnw[c0 + 3], s->lnb[c0 + 3]);
            s->xg[(c0 + 0) * NSEQ + 4 * (rb ^ swz(c0 + 0)) + r0] = v0;
            s->xg[(c0 + 1) * NSEQ + 4 * (rb ^ swz(c0 + 1)) + r0] = v1;
            s->xg[(c0 + 2) * NSEQ + 4 * (rb ^ swz(c0 + 2)) + r0] = v2;
            s->xg[(c0 + 3) * NSEQ + 4 * (rb ^ swz(c0 + 3)) + r0] = v3;
            xacc0 += v0; xacc1 += v1; xacc2 += v2; xacc3 += v3;
        }
        xacc0 += __shfl_xor_sync(0xffffffffu, xacc0, 16);
        xacc1 += __shfl_xor_sync(0xffffffffu, xacc1, 16);
        xacc2 += __shfl_xor_sync(0xffffffffu, xacc2, 16);
        xacc3 += __shfl_xor_sync(0xffffffffu, xacc3, 16);
        if (lane < 16) {
            float* xp = s->xpart + wid * 64 + 4 * lq4;
            xp[0] = xacc0; xp[1] = xacc1; xp[2] = xacc2; xp[3] = xacc3;
        }
    }
    __syncthreads();

    // xsum (consumed after the next barrier)
    if (tid < 64) {
        float t = 0.f;
        #pragma unroll
        for (int w = 0; w < 16; ++w) t += s->xpart[w * 64 + tid];
        s->xsum[tid] = t;
    }

    // ---------------- pass A: FUSED gate + kv GEMM ----------------
    // gate: 8 rows x 8 cols (ga[r][p] = cols 8cg+2p,+1); kv: 8 rows x col-pair (shares splats)
    const int rg = tid >> 3;   // rows 8rg..8rg+7
    const int cg = tid & 7;
    const int r2a = 2 * rg, r2b = 2 * rg + 1;   // row-block indices of the two float4 halves

    ull ga[8][4];
    ull ka[8];
    #pragma unroll
    for (int r = 0; r < 8; ++r) {
        ka[r] = 0;
        #pragma unroll
        for (int p = 0; p < 4; ++p) ga[r][p] = 0;
    }
    #pragma unroll 1
    for (int a = 0; a < 8; ++a) {
        const float* xcol  = s->xg + a * 8 * NSEQ;
        const int ea = (r2a ^ a) << 2;
        const int eb = (r2b ^ a) << 2;
        const float* wg_p  = &s->wc[a * 8][8 * cg];
        const float* wkv_p = &s->wc[a * 8][64 + 2 * cg];
        #pragma unroll
        for (int b = 0; b < 8; ++b) {
            float4 xa = *reinterpret_cast<const float4*>(xcol + b * NSEQ + (ea ^ (b << 2)));
            float4 xb = *reinterpret_cast<const float4*>(xcol + b * NSEQ + (eb ^ (b << 2)));
            ulonglong2 w0 = *reinterpret_cast<const ulonglong2*>(wg_p + b * 80);
            ulonglong2 w1 = *reinterpret_cast<const ulonglong2*>(wg_p + b * 80 + 4);
            ull wk = *reinterpret_cast<const ull*>(wkv_p + b * 80);
            ull t;
            t = splat2(xa.x); ffma2(ga[0][0],t,w0.x); ffma2(ga[0][1],t,w0.y); ffma2(ga[0][2],t,w1.x); ffma2(ga[0][3],t,w1.y); ffma2(ka[0],t,wk);
            t = splat2(xa.y); ffma2(ga[1][0],t,w0.x); ffma2(ga[1][1],t,w0.y); ffma2(ga[1][2],t,w1.x); ffma2(ga[1][3],t,w1.y); ffma2(ka[1],t,wk);
            t = splat2(xa.z); ffma2(ga[2][0],t,w0.x); ffma2(ga[2][1],t,w0.y); ffma2(ga[2][2],t,w1.x); ffma2(ga[2][3],t,w1.y); ffma2(ka[2],t,wk);
            t = splat2(xa.w); ffma2(ga[3][0],t,w0.x); ffma2(ga[3][1],t,w0.y); ffma2(ga[3][2],t,w1.x); ffma2(ga[3][3],t,w1.y); ffma2(ka[3],t,wk);
            t = splat2(xb.x); ffma2(ga[4][0],t,w0.x); ffma2(ga[4][1],t,w0.y); ffma2(ga[4][2],t,w1.x); ffma2(ga[4][3],t,w1.y); ffma2(ka[4],t,wk);
            t = splat2(xb.y); ffma2(ga[5][0],t,w0.x); ffma2(ga[5][1],t,w0.y); ffma2(ga[5][2],t,w1.x); ffma2(ga[5][3],t,w1.y); ffma2(ka[5],t,wk);
            t = splat2(xb.z); ffma2(ga[6][0],t,w0.x); ffma2(ga[6][1],t,w0.y); ffma2(ga[6][2],t,w1.x); ffma2(ga[6][3],t,w1.y); ffma2(ka[6],t,wk);
            t = splat2(xb.w); ffma2(ga[7][0],t,w0.x); ffma2(ga[7][1],t,w0.y); ffma2(ga[7][2],t,w1.x); ffma2(ga[7][3],t,w1.y); ffma2(ka[7],t,wk);
        }
    }
    __syncthreads();   // all xg reads done; safe to overwrite with G

    // gate epilogue: G = sigmoid(P + bg) -> xg (same layout)
    #pragma unroll
    for (int c = 0; c < 8; ++c) {
        int col = 8 * cg + c;
        float bgc = s->bgv[col];
        float g[8];
        #pragma unroll
        for (int r = 0; r < 8; ++r) {
            float lo, hi;
            unpack2(ga[r][c >> 1], lo, hi);
            float v = (c & 1) ? hi : lo;
            g[r] = sigmoid_t(v + bgc);
        }
        float* dst = &s->xg[col * NSEQ];
        *reinterpret_cast<float4*>(dst + 4 * ((2 * rg) ^ swz(col)))     = make_float4(g[0], g[1], g[2], g[3]);
        *reinterpret_cast<float4*>(dst + 4 * ((2 * rg + 1) ^ swz(col))) = make_float4(g[4], g[5], g[6], g[7]);
    }
    // kv epilogue: ka[r] = (col 2cg, col 2cg+1) of row 8rg+r
    if (cg < 4) {
        #pragma unroll
        for (int r = 0; r < 8; ++r)
            *reinterpret_cast<ull*>(&s->kbuf[8 * rg + r][2 * cg]) = ka[r];
    } else {
        int c0 = 2 * cg - 8;
        float a8[8], b8[8];
        #pragma unroll
        for (int r = 0; r < 8; ++r) unpack2(ka[r], a8[r], b8[r]);
        *reinterpret_cast<float4*>(&s->vT[c0 * NSEQ + 8 * rg])           = make_float4(a8[0], a8[1], a8[2], a8[3]);
        *reinterpret_cast<float4*>(&s->vT[c0 * NSEQ + 8 * rg + 4])       = make_float4(a8[4], a8[5], a8[6], a8[7]);
        *reinterpret_cast<float4*>(&s->vT[(c0 + 1) * NSEQ + 8 * rg])     = make_float4(b8[0], b8[1], b8[2], b8[3]);
        *reinterpret_cast<float4*>(&s->vT[(c0 + 1) * NSEQ + 8 * rg + 4]) = make_float4(b8[4], b8[5], b8[6], b8[7]);
    }
    // qvec partials (xsum written before previous barrier)
    {
        int dg = tid >> 6, c = tid & 63;
        float p = 0.f;
        #pragma unroll
        for (int i = 0; i < 8; ++i) p = fmaf(s->xsum[8 * dg + i], wqr[i], p);
        s->xpart[dg * 64 + c] = p;
    }
    __syncthreads();

    if (tid < 64) {
        float q = 0.f;
        #pragma unroll
        for (int dg = 0; dg < 8; ++dg) q += s->xpart[dg * 64 + tid];
        s->qvec[tid] = q * (float)(0.35355339059327373 / 512.0); // (1/sqrt(8))/N
    }
    __syncthreads();

    // ---------------- scores[h][n] ----------------
    {
        float4 k0 = *reinterpret_cast<const float4*>(&s->kbuf[tid][0]);
        float4 k1 = *reinterpret_cast<const float4*>(&s->kbuf[tid][4]);
        #pragma unroll
        for (int h = 0; h < 8; ++h) {
            const float* qf = &s->qvec[h * 8];
            float sc = qf[0]*k0.x + qf[1]*k0.y + qf[2]*k0.z + qf[3]*k0.w
                     + qf[4]*k1.x + qf[5]*k1.y + qf[6]*k1.z + qf[7]*k1.w;
            s->scores[h * NSEQ + tid] = sc;
        }
    }
    __syncthreads();

    // ---------------- softmax partials: 2 warps per head ----------------
    {
        int h = wid >> 1, half = wid & 1;
        const float* sc = s->scores + h * NSEQ + half * 256;
        float sv[8], m = -1e30f;
        #pragma unroll
        for (int k = 0; k < 8; ++k) { sv[k] = sc[lane + 32 * k]; m = fmaxf(m, sv[k]); }
        #pragma unroll
        for (int off = 16; off > 0; off >>= 1)
            m = fmaxf(m, __shfl_xor_sync(0xffffffffu, m, off));
        float ssum = 0.f, acc[8];
        #pragma unroll
        for (int d = 0; d < 8; ++d) acc[d] = 0.f;
        #pragma unroll
        for (int k = 0; k < 8; ++k) {
            float e = __expf(sv[k] - m);
            ssum += e;
            int n = half * 256 + lane + 32 * k;
            #pragma unroll
            for (int d = 0; d < 8; ++d) acc[d] = fmaf(e, s->vT[d * NSEQ + n], acc[d]);
        }
        #pragma unroll
        for (int off = 16; off > 0; off >>= 1) {
            ssum += __shfl_xor_sync(0xffffffffu, ssum, off);
            #pragma unroll
            for (int d = 0; d < 8; ++d) acc[d] += __shfl_xor_sync(0xffffffffu, acc[d], off);
        }
        if (lane == 0) {
            s->mpart[wid] = m;
            s->spart[wid] = ssum;
            #pragma unroll
            for (int d = 0; d < 8; ++d) s->opart[wid][d] = acc[d];
        }
    }
    __syncthreads();

    // ovec combine (exact two-way softmax merge)
    if (tid < 64) {
        int h = tid >> 3, d = tid & 7;
        float m0 = s->mpart[2 * h], m1 = s->mpart[2 * h + 1];
        float m = fmaxf(m0, m1);
        float e0 = __expf(m0 - m), e1 = __expf(m1 - m);
        float ss = s->spart[2 * h] * e0 + s->spart[2 * h + 1] * e1;
        float ov = s->opart[2 * h][d] * e0 + s->opart[2 * h + 1][d] * e1;
        s->ovec[8 * h + d] = ov / ss;
    }
    __syncthreads();

    // fold ovec into Wo rows
    #pragma unroll
    for (int i = 0; i < 2; ++i) {
        int idx = tid + i * NT;
        float4 w4 = ((float4*)s->wo)[idx];
        float ov = s->ovec[idx >> 4];
        w4.x *= ov; w4.y *= ov; w4.z *= ov; w4.w *= ov;
        ((float4*)s->wo)[idx] = w4;
    }
    __syncthreads();

    // ---------------- pass B: out = G @ Wo' + bo ----------------
    {
        ull acc[8][4];
        #pragma unroll
        for (int i = 0; i < 8; ++i)
            #pragma unroll
            for (int p = 0; p < 4; ++p) acc[i][p] = 0;

        #pragma unroll 1
        for (int a = 0; a < 8; ++a) {
            const float* gcol = s->xg + a * 8 * NSEQ;
            const int ea = (r2a ^ a) << 2;
            const int eb = (r2b ^ a) << 2;
            const float* wo_p = s->wo + (a * 8) * 64 + 8 * cg;
            #pragma unroll
            for (int b = 0; b < 8; ++b) {
                float4 xa = *reinterpret_cast<const float4*>(gcol + b * NSEQ + (ea ^ (b << 2)));
                float4 xb = *reinterpret_cast<const float4*>(gcol + b * NSEQ + (eb ^ (b << 2)));
                ulonglong2 wA = *reinterpret_cast<const ulonglong2*>(wo_p + b * 64);
                ulonglong2 wB = *reinterpret_cast<const ulonglong2*>(wo_p + b * 64 + 4);
                ull t;
                t = splat2(xa.x); ffma2(acc[0][0],t,wA.x); ffma2(acc[0][1],t,wA.y); ffma2(acc[0][2],t,wB.x); ffma2(acc[0][3],t,wB.y);
                t = splat2(xa.y); ffma2(acc[1][0],t,wA.x); ffma2(acc[1][1],t,wA.y); ffma2(acc[1][2],t,wB.x); ffma2(acc[1][3],t,wB.y);
                t = splat2(xa.z); ffma2(acc[2][0],t,wA.x); ffma2(acc[2][1],t,wA.y); ffma2(acc[2][2],t,wB.x); ffma2(acc[2][3],t,wB.y);
                t = splat2(xa.w); ffma2(acc[3][0],t,wA.x); ffma2(acc[3][1],t,wA.y); ffma2(acc[3][2],t,wB.x); ffma2(acc[3][3],t,wB.y);
                t = splat2(xb.x); ffma2(acc[4][0],t,wA.x); ffma2(acc[4][1],t,wA.y); ffma2(acc[4][2],t,wB.x); ffma2(acc[4][3],t,wB.y);
                t = splat2(xb.y); ffma2(acc[5][0],t,wA.x); ffma2(acc[5][1],t,wA.y); ffma2(acc[5][2],t,wB.x); ffma2(acc[5][3],t,wB.y);
                t = splat2(xb.z); ffma2(acc[6][0],t,wA.x); ffma2(acc[6][1],t,wA.y); ffma2(acc[6][2],t,wB.x); ffma2(acc[6][3],t,wB.y);
                t = splat2(xb.w); ffma2(acc[7][0],t,wA.x); ffma2(acc[7][1],t,wA.y); ffma2(acc[7][2],t,wB.x); ffma2(acc[7][3],t,wB.y);
            }
        }

        const ulonglong2 boA = *reinterpret_cast<const ulonglong2*>(&s->bov[8 * cg]);
        const ulonglong2 boB = *reinterpret_cast<const ulonglong2*>(&s->bov[8 * cg + 4]);
        #pragma unroll
        for (int i = 0; i < 8; ++i) {
            size_t row = (size_t)(8 * rg + i);
            float* op = out + (row * LRES + l) * 64 + 8 * cg;
            ulonglong2 v0, v1;
            v0.x = add2(acc[i][0], boA.x); v0.y = add2(acc[i][1], boA.y);
            v1.x = add2(acc[i][2], boB.x); v1.y = add2(acc[i][3], boB.y);
            *reinterpret_cast<ulonglong2*>(op)     = v0;
            *reinterpret_cast<ulonglong2*>(op + 4) = v1;
        }
    }
}

extern "C" void kernel_launch(void* const* d_in, const int* in_sizes, int n_in,
                              void* d_out, int out_size) {
    const float* msa = (const float*)d_in[0];
    const float* lnw = (const float*)d_in[1];
    const float* lnb = (const float*)d_in[2];
    const float* wq  = (const float*)d_in[3];
    const float* wk  = (const float*)d_in[4];
    const float* wv  = (const float*)d_in[5];
    const float* wg  = (const float*)d_in[6];
    const float* bg  = (const float*)d_in[7];
    const float* wo  = (const float*)d_in[8];
    const float* bo  = (const float*)d_in[9];
    float* out = (float*)d_out;

    const int smem_bytes = (int)sizeof(Smem);
    cudaFuncSetAttribute(msa_col_attn_v11,
                         cudaFuncAttributeMaxDynamicSharedMemorySize, smem_bytes);
    msa_col_attn_v11<<<LRES, NT, smem_bytes>>>(
        msa, lnw, lnb, wq, wk, wv, wg, bg, wo, bo, out);
}